// round 4
// baseline (speedup 1.0000x reference)
#include <cuda_runtime.h>
#include <cuda_bf16.h>
#include <cstdint>

// Embedding gather via TMA bulk copies, v2:
//   out[row, :] = weight[ids[row], :],  row = 3072 B.
// 16 rows per single-warp CTA. Read side: 16 per-row cp.async.bulk G->S
// (scattered gather), ONE mbarrier with expect_tx = 48KB. Write side:
// output rows are CONTIGUOUS -> one single 48KB cp.async.bulk S->G.

static constexpr int DIM          = 768;
static constexpr int ROW_BYTES    = DIM * 4;                    // 3072
static constexpr int ROWS_PER_CTA = 16;
static constexpr int BUF_BYTES    = ROWS_PER_CTA * ROW_BYTES;   // 49152

__global__ __launch_bounds__(32) void emb_tma_kernel(
    const int* __restrict__ ids,
    const float* __restrict__ weight,
    float* __restrict__ out)
{
    __shared__ __align__(128) unsigned char buf[BUF_BYTES];
    __shared__ __align__(8)  unsigned long long mbar;

    const int base = blockIdx.x * ROWS_PER_CTA;
    if (threadIdx.x != 0) return;

    uint32_t smem_buf  = (uint32_t)__cvta_generic_to_shared(buf);
    uint32_t smem_mbar = (uint32_t)__cvta_generic_to_shared(&mbar);

    asm volatile("mbarrier.init.shared.b64 [%0], 1;" :: "r"(smem_mbar) : "memory");
    asm volatile("fence.proxy.async.shared::cta;" ::: "memory");

    // Preload ids (independent; ids array is tiny and L2-hot).
    int id[ROWS_PER_CTA];
#pragma unroll
    for (int s = 0; s < ROWS_PER_CTA; s++)
        id[s] = __ldg(&ids[base + s]);

    // One expect_tx for the whole 48KB batch, then 16 G->S gathers.
    asm volatile("mbarrier.arrive.expect_tx.shared.b64 _, [%0], %1;"
                 :: "r"(smem_mbar), "r"(BUF_BYTES) : "memory");
#pragma unroll
    for (int s = 0; s < ROWS_PER_CTA; s++) {
        uint32_t dst = smem_buf + s * ROW_BYTES;
        const void* src = (const char*)weight + (size_t)id[s] * ROW_BYTES;
        asm volatile(
            "cp.async.bulk.shared::cta.global.mbarrier::complete_tx::bytes "
            "[%0], [%1], %2, [%3];"
            :: "r"(dst), "l"(src), "r"(ROW_BYTES), "r"(smem_mbar) : "memory");
    }

    // Single wait for all 16 rows.
    {
        uint32_t done = 0;
        while (!done) {
            asm volatile(
                "{\n\t"
                ".reg .pred p;\n\t"
                "mbarrier.try_wait.parity.acquire.cta.shared::cta.b64 p, [%1], 0, 0x989680;\n\t"
                "selp.b32 %0, 1, 0, p;\n\t"
                "}"
                : "=r"(done) : "r"(smem_mbar) : "memory");
        }
    }

    // Output rows are contiguous: ONE 48KB bulk store.
    void* dstg = (char*)out + (size_t)base * ROW_BYTES;
    asm volatile(
        "cp.async.bulk.global.shared::cta.bulk_group [%0], [%1], %2;"
        :: "l"(dstg), "r"(smem_buf), "r"(BUF_BYTES) : "memory");
    asm volatile("cp.async.bulk.commit_group;" ::: "memory");
    asm volatile("cp.async.bulk.wait_group 0;" ::: "memory");
}

extern "C" void kernel_launch(void* const* d_in, const int* in_sizes, int n_in,
                              void* d_out, int out_size)
{
    const int*   ids    = (const int*)d_in[0];     // [8192] int32
    const float* weight = (const float*)d_in[1];   // [32000, 768] f32
    float*       out    = (float*)d_out;           // [8192, 768] f32

    const int n_rows = in_sizes[0];                // 8192
    const int n_ctas = n_rows / ROWS_PER_CTA;      // 512
    emb_tma_kernel<<<n_ctas, 32>>>(ids, weight, out);
}

// round 5
// speedup vs baseline: 1.1706x; 1.1706x over previous
#include <cuda_runtime.h>
#include <cuda_bf16.h>
#include <cstdint>

// Embedding gather via lane-parallel TMA bulk copies:
//   out[row, :] = weight[ids[row], :],  row = 3072 B.
// 8 rows per CTA, one LANE per row. Each lane owns its mbarrier + smem
// slice: init -> id load -> G2S bulk -> wait own row -> S2G bulk -> drain.
// All 8 pipelines run in parallel; no cross-lane sync at all.

static constexpr int DIM          = 768;
static constexpr int ROW_BYTES    = DIM * 4;                    // 3072
static constexpr int ROWS_PER_CTA = 8;
static constexpr int BUF_BYTES    = ROWS_PER_CTA * ROW_BYTES;   // 24576

__global__ __launch_bounds__(32) void emb_tma_kernel(
    const int* __restrict__ ids,
    const float* __restrict__ weight,
    float* __restrict__ out)
{
    __shared__ __align__(128) unsigned char buf[BUF_BYTES];
    __shared__ __align__(8)  unsigned long long mbar[ROWS_PER_CTA];

    const int lane = threadIdx.x;
    if (lane >= ROWS_PER_CTA) return;

    const int row = blockIdx.x * ROWS_PER_CTA + lane;

    uint32_t mb = (uint32_t)__cvta_generic_to_shared(&mbar[lane]);
    uint32_t sb = (uint32_t)__cvta_generic_to_shared(buf) + lane * ROW_BYTES;

    // Each lane inits its own barrier; same-thread init->fence->TMA ordering.
    asm volatile("mbarrier.init.shared.b64 [%0], 1;" :: "r"(mb) : "memory");
    asm volatile("fence.proxy.async.shared::cta;" ::: "memory");

    // Coalesced id load (8 lanes, one transaction).
    const int id = __ldg(&ids[row]);

    // G->S gather of this lane's row.
    asm volatile("mbarrier.arrive.expect_tx.shared.b64 _, [%0], %1;"
                 :: "r"(mb), "r"(ROW_BYTES) : "memory");
    {
        const void* src = (const char*)weight + (size_t)id * ROW_BYTES;
        asm volatile(
            "cp.async.bulk.shared::cta.global.mbarrier::complete_tx::bytes "
            "[%0], [%1], %2, [%3];"
            :: "r"(sb), "l"(src), "r"(ROW_BYTES), "r"(mb) : "memory");
    }

    // Wait only for OWN row.
    {
        uint32_t done = 0;
        while (!done) {
            asm volatile(
                "{\n\t"
                ".reg .pred p;\n\t"
                "mbarrier.try_wait.parity.acquire.cta.shared::cta.b64 p, [%1], 0, 0x989680;\n\t"
                "selp.b32 %0, 1, 0, p;\n\t"
                "}"
                : "=r"(done) : "r"(mb) : "memory");
        }
    }

    // S->G store of this lane's row; drain own bulk group before exit
    // (SMEM must outlive the store's reads).
    {
        void* dstg = (char*)out + (size_t)row * ROW_BYTES;
        asm volatile(
            "cp.async.bulk.global.shared::cta.bulk_group [%0], [%1], %2;"
            :: "l"(dstg), "r"(sb), "r"(ROW_BYTES) : "memory");
    }
    asm volatile("cp.async.bulk.commit_group;" ::: "memory");
    asm volatile("cp.async.bulk.wait_group 0;" ::: "memory");
}

extern "C" void kernel_launch(void* const* d_in, const int* in_sizes, int n_in,
                              void* d_out, int out_size)
{
    const int*   ids    = (const int*)d_in[0];     // [8192] int32
    const float* weight = (const float*)d_in[1];   // [32000, 768] f32
    float*       out    = (float*)d_out;           // [8192, 768] f32

    const int n_rows = in_sizes[0];                // 8192
    const int n_ctas = n_rows / ROWS_PER_CTA;      // 1024
    emb_tma_kernel<<<n_ctas, 32>>>(ids, weight, out);
}

// round 6
// speedup vs baseline: 1.2610x; 1.0772x over previous
#include <cuda_runtime.h>
#include <cuda_bf16.h>
#include <cstdint>

// Embedding gather via TMA bulk copies + L2 cache policies:
//   out[row, :] = weight[ids[row], :],  row = 3072 B.
// R3 structure (best measured): 8 rows per single-warp CTA, per-row
// mbarrier, store each row as it lands. New: weight reads use
// L2::evict_last (keep the 98MB table resident), out stores use
// L2::evict_first (write-once data must not evict weight).

static constexpr int DIM          = 768;
static constexpr int ROW_BYTES    = DIM * 4;                    // 3072
static constexpr int ROWS_PER_CTA = 8;
static constexpr int BUF_BYTES    = ROWS_PER_CTA * ROW_BYTES;   // 24576

__global__ __launch_bounds__(32) void emb_tma_kernel(
    const int* __restrict__ ids,
    const float* __restrict__ weight,
    float* __restrict__ out)
{
    __shared__ __align__(128) unsigned char buf[BUF_BYTES];
    __shared__ __align__(8)  unsigned long long mbar[ROWS_PER_CTA];

    const int base = blockIdx.x * ROWS_PER_CTA;
    if (threadIdx.x != 0) return;

    uint32_t smem_buf  = (uint32_t)__cvta_generic_to_shared(buf);
    uint32_t smem_mbar = (uint32_t)__cvta_generic_to_shared(mbar);

    // L2 policies: keep weight, stream out.
    uint64_t pol_keep, pol_stream;
    asm volatile("createpolicy.fractional.L2::evict_last.b64 %0, 1.0;"
                 : "=l"(pol_keep));
    asm volatile("createpolicy.fractional.L2::evict_first.b64 %0, 1.0;"
                 : "=l"(pol_stream));

#pragma unroll
    for (int s = 0; s < ROWS_PER_CTA; s++) {
        asm volatile("mbarrier.init.shared.b64 [%0], 1;"
                     :: "r"(smem_mbar + s * 8) : "memory");
    }
    asm volatile("fence.proxy.async.shared::cta;" ::: "memory");

    int id[ROWS_PER_CTA];
#pragma unroll
    for (int s = 0; s < ROWS_PER_CTA; s++)
        id[s] = __ldg(&ids[base + s]);

    // G->S gathers, weight kept in L2 (evict_last).
#pragma unroll
    for (int s = 0; s < ROWS_PER_CTA; s++) {
        uint32_t mb  = smem_mbar + s * 8;
        uint32_t dst = smem_buf + s * ROW_BYTES;
        const void* src = (const char*)weight + (size_t)id[s] * ROW_BYTES;
        asm volatile("mbarrier.arrive.expect_tx.shared.b64 _, [%0], %1;"
                     :: "r"(mb), "r"(ROW_BYTES) : "memory");
        asm volatile(
            "cp.async.bulk.shared::cta.global.mbarrier::complete_tx::bytes"
            ".L2::cache_hint [%0], [%1], %2, [%3], %4;"
            :: "r"(dst), "l"(src), "r"(ROW_BYTES), "r"(mb), "l"(pol_keep)
            : "memory");
    }

    // Store rows as they land; out streams through L2 (evict_first).
#pragma unroll
    for (int s = 0; s < ROWS_PER_CTA; s++) {
        uint32_t mb = smem_mbar + s * 8;
        uint32_t done = 0;
        while (!done) {
            asm volatile(
                "{\n\t"
                ".reg .pred p;\n\t"
                "mbarrier.try_wait.parity.acquire.cta.shared::cta.b64 p, [%1], 0, 0x989680;\n\t"
                "selp.b32 %0, 1, 0, p;\n\t"
                "}"
                : "=r"(done) : "r"(mb) : "memory");
        }
        void* dstg = (char*)out + (size_t)(base + s) * ROW_BYTES;
        uint32_t srcs = smem_buf + s * ROW_BYTES;
        asm volatile(
            "cp.async.bulk.global.shared::cta.bulk_group.L2::cache_hint "
            "[%0], [%1], %2, %3;"
            :: "l"(dstg), "r"(srcs), "r"(ROW_BYTES), "l"(pol_stream)
            : "memory");
    }
    asm volatile("cp.async.bulk.commit_group;" ::: "memory");
    asm volatile("cp.async.bulk.wait_group 0;" ::: "memory");
}

extern "C" void kernel_launch(void* const* d_in, const int* in_sizes, int n_in,
                              void* d_out, int out_size)
{
    const int*   ids    = (const int*)d_in[0];     // [8192] int32
    const float* weight = (const float*)d_in[1];   // [32000, 768] f32
    float*       out    = (float*)d_out;           // [8192, 768] f32

    const int n_rows = in_sizes[0];                // 8192
    const int n_ctas = n_rows / ROWS_PER_CTA;      // 1024
    emb_tma_kernel<<<n_ctas, 32>>>(ids, weight, out);
}

// round 9
// speedup vs baseline: 1.2657x; 1.0037x over previous
#include <cuda_runtime.h>
#include <cuda_bf16.h>
#include <cstdint>

// Embedding gather: TMA bulk G->S gather + hinted register STG stores.
//   out[row, :] = weight[ids[row], :], row = 3072 B.
// 8 rows per CTA (1024 CTAs, 192 threads). Thread 0 issues 8 G->S bulk
// copies (two mbarriers, 4 rows each). All threads wait half A, store
// 12KB coalesced with st.global.L2::cache_hint (evict_first) so output
// writes do NOT evict the 98MB weight table from the 126MB L2; then half B.

static constexpr int DIM       = 768;
static constexpr int VEC       = DIM / 4;                 // 192 float4/row
static constexpr int ROW_BYTES = DIM * 4;                 // 3072
static constexpr int ROWS      = 8;
static constexpr int HALF_ROWS = ROWS / 2;                // 4
static constexpr int HALF_BYTES = HALF_ROWS * ROW_BYTES;  // 12288
static constexpr int BUF_BYTES = ROWS * ROW_BYTES;        // 24576
static constexpr int THREADS   = VEC;                     // 192

__global__ __launch_bounds__(THREADS) void emb_kernel(
    const int* __restrict__ ids,
    const float* __restrict__ weight,
    float* __restrict__ out)
{
    __shared__ __align__(128) unsigned char buf[BUF_BYTES];
    __shared__ __align__(8)  unsigned long long mbar[2];

    const int base = blockIdx.x * ROWS;
    const int t    = threadIdx.x;

    uint32_t sb  = (uint32_t)__cvta_generic_to_shared(buf);
    uint32_t mb0 = (uint32_t)__cvta_generic_to_shared(&mbar[0]);
    uint32_t mb1 = mb0 + 8;

    if (t == 0) {
        asm volatile("mbarrier.init.shared.b64 [%0], 1;" :: "r"(mb0) : "memory");
        asm volatile("mbarrier.init.shared.b64 [%0], 1;" :: "r"(mb1) : "memory");
        asm volatile("fence.proxy.async.shared::cta;" ::: "memory");
    }
    __syncthreads();   // mbarrier init visible to all waiters

    if (t == 0) {
        int id[ROWS];
#pragma unroll
        for (int s = 0; s < ROWS; s++)
            id[s] = __ldg(&ids[base + s]);

        asm volatile("mbarrier.arrive.expect_tx.shared.b64 _, [%0], %1;"
                     :: "r"(mb0), "r"(HALF_BYTES) : "memory");
#pragma unroll
        for (int s = 0; s < HALF_ROWS; s++) {
            const void* src = (const char*)weight + (size_t)id[s] * ROW_BYTES;
            asm volatile(
                "cp.async.bulk.shared::cta.global.mbarrier::complete_tx::bytes "
                "[%0], [%1], %2, [%3];"
                :: "r"(sb + s * ROW_BYTES), "l"(src), "r"(ROW_BYTES), "r"(mb0)
                : "memory");
        }
        asm volatile("mbarrier.arrive.expect_tx.shared.b64 _, [%0], %1;"
                     :: "r"(mb1), "r"(HALF_BYTES) : "memory");
#pragma unroll
        for (int s = HALF_ROWS; s < ROWS; s++) {
            const void* src = (const char*)weight + (size_t)id[s] * ROW_BYTES;
            asm volatile(
                "cp.async.bulk.shared::cta.global.mbarrier::complete_tx::bytes "
                "[%0], [%1], %2, [%3];"
                :: "r"(sb + s * ROW_BYTES), "l"(src), "r"(ROW_BYTES), "r"(mb1)
                : "memory");
        }
    }

    // Streaming (evict_first) policy for output stores.
    uint64_t pol;
    asm volatile("createpolicy.fractional.L2::evict_first.b64 %0, 1.0;" : "=l"(pol));

    const float4* sbuf = (const float4*)buf;
    float4*       o4   = (float4*)out + (size_t)base * VEC;

    // ---- half A: rows [0,4) ----
    {
        uint32_t done = 0;
        while (!done) {
            asm volatile(
                "{\n\t.reg .pred p;\n\t"
                "mbarrier.try_wait.parity.acquire.cta.shared::cta.b64 p, [%1], 0, 0x989680;\n\t"
                "selp.b32 %0, 1, 0, p;\n\t}"
                : "=r"(done) : "r"(mb0) : "memory");
        }
    }
#pragma unroll
    for (int k = 0; k < HALF_ROWS; k++) {
        int i = k * THREADS + t;          // 0..767, coalesced
        float4 v = sbuf[i];
        asm volatile(
            "st.global.L2::cache_hint.v4.f32 [%0], {%1,%2,%3,%4}, %5;"
            :: "l"(o4 + i), "f"(v.x), "f"(v.y), "f"(v.z), "f"(v.w), "l"(pol)
            : "memory");
    }

    // ---- half B: rows [4,8) ----
    {
        uint32_t done = 0;
        while (!done) {
            asm volatile(
                "{\n\t.reg .pred p;\n\t"
                "mbarrier.try_wait.parity.acquire.cta.shared::cta.b64 p, [%1], 0, 0x989680;\n\t"
                "selp.b32 %0, 1, 0, p;\n\t}"
                : "=r"(done) : "r"(mb1) : "memory");
        }
    }
#pragma unroll
    for (int k = 0; k < HALF_ROWS; k++) {
        int i = HALF_ROWS * THREADS + k * THREADS + t;   // 768..1535
        float4 v = sbuf[i];
        asm volatile(
            "st.global.L2::cache_hint.v4.f32 [%0], {%1,%2,%3,%4}, %5;"
            :: "l"(o4 + i), "f"(v.x), "f"(v.y), "f"(v.z), "f"(v.w), "l"(pol)
            : "memory");
    }
}

extern "C" void kernel_launch(void* const* d_in, const int* in_sizes, int n_in,
                              void* d_out, int out_size)
{
    const int*   ids    = (const int*)d_in[0];     // [8192] int32
    const float* weight = (const float*)d_in[1];   // [32000, 768] f32
    float*       out    = (float*)d_out;           // [8192, 768] f32

    const int n_rows = in_sizes[0];                // 8192
    const int n_ctas = n_rows / ROWS;              // 1024
    emb_kernel<<<n_ctas, THREADS>>>(ids, weight, out);
}